// round 1
// baseline (speedup 1.0000x reference)
#include <cuda_runtime.h>
#include <cfloat>
#include <cstdint>

// Residual VQ, fused single-kernel implementation.
// N = 32768 rows of D=128; 8 codebooks of K=1024.
// Each CTA owns MT=64 rows for the whole pipeline (residual lives in smem),
// so no inter-CTA synchronization is needed.

#define NCB   8
#define KCB   1024
#define DIM   128
#define NROWS 32768
#define MT    64          // rows per CTA
#define KT    128         // codes per K-tile
#define NTHR  256
#define NCTA  (NROWS / MT)   // 512

#define CODES_ELEMS (NROWS * NCB)     // 262144
#define Q_ELEMS     (NROWS * DIM)     // 4194304

struct SmemT {
    float  W[DIM][KT];        // codebook tile, transposed [d][k]   64 KB
    float  Rt[DIM][MT];       // residual, transposed [d][m]        32 KB
    float  sqcpart[2][KT];    //                                      1 KB
    float  sqc[KT];           //                                    0.5 KB
    float  Apart[4][MT];      //                                      1 KB
    float  Arow[MT];          //                                    256 B
    int    codes_sm[NCB][MT]; //                                      2 KB
    double lred[NTHR];        //                                      2 KB
};

__device__ double g_loss;

__global__ void rvq_zero_kernel() { g_loss = 0.0; }

__global__ void rvq_finish_kernel(float* loss_out) {
    // loss = total_sum / (N*D) / NCB
    *loss_out = (float)(g_loss * (1.0 / ((double)Q_ELEMS * (double)NCB)));
}

__global__ __launch_bounds__(NTHR, 2)
void rvq_main_kernel(const float* __restrict__ emb,
                     const float* __restrict__ cbs,
                     float* __restrict__ codes_f,
                     int*   __restrict__ codes_i,
                     float* __restrict__ qout,
                     int do_loss) {
    extern __shared__ char smem_raw[];
    SmemT& s = *reinterpret_cast<SmemT*>(smem_raw);

    const int tid  = threadIdx.x;
    const int row0 = blockIdx.x * MT;

    // ------------------------------------------------------------------
    // Load embeddings for our 64 rows, transposed into Rt[d][m].
    // mapping: f = tid + 256*i (i<8); m = f & 63, d4 = f >> 6 (0..31)
    // ------------------------------------------------------------------
    #pragma unroll
    for (int i = 0; i < 8; i++) {
        int f  = tid + NTHR * i;
        int m  = f & 63;
        int d4 = f >> 6;
        float4 v = __ldg(reinterpret_cast<const float4*>(
            emb + (size_t)(row0 + m) * DIM + d4 * 4));
        s.Rt[d4 * 4 + 0][m] = v.x;
        s.Rt[d4 * 4 + 1][m] = v.y;
        s.Rt[d4 * 4 + 2][m] = v.z;
        s.Rt[d4 * 4 + 3][m] = v.w;
    }
    __syncthreads();

    // Initial A[m] = sum_d r^2
    {
        int m  = tid & 63;
        int dc = tid >> 6;     // 0..3, each owns 32 d's
        float a = 0.f;
        #pragma unroll
        for (int i = 0; i < 32; i++) {
            float v = s.Rt[dc * 32 + i][m];
            a = __fmaf_rn(v, v, a);
        }
        s.Apart[dc][m] = a;
    }
    __syncthreads();
    if (tid < MT)
        s.Arow[tid] = ((s.Apart[0][tid] + s.Apart[1][tid]) + s.Apart[2][tid]) + s.Apart[3][tid];
    __syncthreads();

    double lacc = 0.0;

    const int tk = tid & 31;      // 0..31 : k-column group (one warp per tid_m)
    const int tm = tid >> 5;      // 0..7  : m-row group
    const int mb = tm * 8;

    // ------------------------------------------------------------------
    // Codebook loop (sequential dependency)
    // ------------------------------------------------------------------
    for (int c = 0; c < NCB; c++) {
        const float* cbase = cbs + (size_t)c * KCB * DIM;

        float mval[8];
        int   midx[8];
        #pragma unroll
        for (int r = 0; r < 8; r++) { mval[r] = FLT_MAX; midx[r] = 0; }

        float Areg[8];
        #pragma unroll
        for (int r = 0; r < 8; r++) Areg[r] = s.Arow[mb + r];

        for (int kt = 0; kt < KCB / KT; kt++) {
            __syncthreads();   // previous tile's compute done before overwrite

            // ---- load W tile transposed: W[d][k], k = tid&127, d4 = (tid>>7)+2i
            {
                const int kl = tid & 127;
                const int hh = tid >> 7;
                float sq = 0.f;
                const float* src = cbase + (size_t)(kt * KT + kl) * DIM;
                #pragma unroll
                for (int i = 0; i < 16; i++) {
                    int d4 = hh + 2 * i;
                    float4 v = __ldg(reinterpret_cast<const float4*>(src + d4 * 4));
                    s.W[d4 * 4 + 0][kl] = v.x;
                    s.W[d4 * 4 + 1][kl] = v.y;
                    s.W[d4 * 4 + 2][kl] = v.z;
                    s.W[d4 * 4 + 3][kl] = v.w;
                    sq = __fmaf_rn(v.x, v.x, sq);
                    sq = __fmaf_rn(v.y, v.y, sq);
                    sq = __fmaf_rn(v.z, v.z, sq);
                    sq = __fmaf_rn(v.w, v.w, sq);
                }
                s.sqcpart[hh][kl] = sq;
            }
            __syncthreads();
            if (tid < KT) s.sqc[tid] = s.sqcpart[0][tid] + s.sqcpart[1][tid];
            __syncthreads();

            // ---- GEMM micro-tile: 8 rows x 4 codes per thread, full D=128
            float acc[8][4];
            #pragma unroll
            for (int r = 0; r < 8; r++)
                #pragma unroll
                for (int j = 0; j < 4; j++) acc[r][j] = 0.f;

            const float* pr = &s.Rt[0][mb];
            const float* pw = &s.W[0][tk * 4];
            #pragma unroll 8
            for (int d = 0; d < DIM; d++) {
                float4 ra = *reinterpret_cast<const float4*>(pr);
                float4 rb = *reinterpret_cast<const float4*>(pr + 4);
                float4 wv = *reinterpret_cast<const float4*>(pw);
                pr += MT;
                pw += KT;
                float rr[8] = {ra.x, ra.y, ra.z, ra.w, rb.x, rb.y, rb.z, rb.w};
                float ww[4] = {wv.x, wv.y, wv.z, wv.w};
                #pragma unroll
                for (int r = 0; r < 8; r++)
                    #pragma unroll
                    for (int j = 0; j < 4; j++)
                        acc[r][j] = __fmaf_rn(rr[r], ww[j], acc[r][j]);
            }

            // ---- fold into running argmin (k ascending -> first-index tie-break)
            #pragma unroll
            for (int j = 0; j < 4; j++) {
                int   kg = kt * KT + tk * 4 + j;
                float sq = s.sqc[tk * 4 + j];
                #pragma unroll
                for (int r = 0; r < 8; r++) {
                    // d2 = (A - 2*dot) + sqc   (matches reference expression order)
                    float d2 = __fadd_rn(__fmaf_rn(-2.f, acc[r][j], Areg[r]), sq);
                    if (d2 < mval[r]) { mval[r] = d2; midx[r] = kg; }
                }
            }
        }

        // ---- warp argmin reduction over the 32 k-lanes (tie -> smaller index)
        #pragma unroll
        for (int off = 16; off >= 1; off >>= 1) {
            #pragma unroll
            for (int r = 0; r < 8; r++) {
                float ov = __shfl_xor_sync(0xffffffffu, mval[r], off);
                int   oi = __shfl_xor_sync(0xffffffffu, midx[r], off);
                if (ov < mval[r] || (ov == mval[r] && oi < midx[r])) {
                    mval[r] = ov; midx[r] = oi;
                }
            }
        }
        if (tk == 0) {
            #pragma unroll
            for (int r = 0; r < 8; r++) s.codes_sm[c][mb + r] = midx[r];
        }
        __syncthreads();

        // ---- residual update, loss accumulation, next-codebook A
        {
            int m  = tid & 63;
            int dc = tid >> 6;
            int idx = s.codes_sm[c][m];
            const float4* cp = reinterpret_cast<const float4*>(
                cbase + (size_t)idx * DIM + dc * 32);
            float apart = 0.f;
            #pragma unroll
            for (int i = 0; i < 8; i++) {
                float4 cv = __ldg(cp + i);
                int d = dc * 32 + i * 4;
                float r0 = __fadd_rn(s.Rt[d + 0][m], -cv.x);
                float r1 = __fadd_rn(s.Rt[d + 1][m], -cv.y);
                float r2 = __fadd_rn(s.Rt[d + 2][m], -cv.z);
                float r3 = __fadd_rn(s.Rt[d + 3][m], -cv.w);
                s.Rt[d + 0][m] = r0;
                s.Rt[d + 1][m] = r1;
                s.Rt[d + 2][m] = r2;
                s.Rt[d + 3][m] = r3;
                apart = __fmaf_rn(r0, r0, apart);
                apart = __fmaf_rn(r1, r1, apart);
                apart = __fmaf_rn(r2, r2, apart);
                apart = __fmaf_rn(r3, r3, apart);
                lacc += (double)(r0 * r0) + (double)(r1 * r1)
                      + (double)(r2 * r2) + (double)(r3 * r3);
            }
            s.Apart[dc][m] = apart;
        }
        __syncthreads();
        if (tid < MT)
            s.Arow[tid] = ((s.Apart[0][tid] + s.Apart[1][tid]) + s.Apart[2][tid]) + s.Apart[3][tid];
        __syncthreads();
    }

    // ------------------------------------------------------------------
    // Outputs
    // ------------------------------------------------------------------
    // codes [N, NCB]
    if (codes_f != nullptr) {
        for (int v = tid; v < MT * NCB; v += NTHR) {
            int m = v >> 3, c = v & 7;
            codes_f[(size_t)(row0 + m) * NCB + c] = (float)s.codes_sm[c][m];
        }
    }
    if (codes_i != nullptr) {
        for (int v = tid; v < MT * NCB; v += NTHR) {
            int m = v >> 3, c = v & 7;
            codes_i[(size_t)(row0 + m) * NCB + c] = s.codes_sm[c][m];
        }
    }

    // quantized = e + (q - e), q accumulated in codebook order
    if (qout != nullptr) {
        int m  = tid & 63;
        int dc = tid >> 6;
        float q[32];
        #pragma unroll
        for (int i = 0; i < 32; i++) q[i] = 0.f;
        for (int c = 0; c < NCB; c++) {
            int idx = s.codes_sm[c][m];
            const float4* cp = reinterpret_cast<const float4*>(
                cbs + (size_t)c * KCB * DIM + (size_t)idx * DIM + dc * 32);
            #pragma unroll
            for (int i = 0; i < 8; i++) {
                float4 cv = __ldg(cp + i);
                q[i * 4 + 0] = __fadd_rn(q[i * 4 + 0], cv.x);
                q[i * 4 + 1] = __fadd_rn(q[i * 4 + 1], cv.y);
                q[i * 4 + 2] = __fadd_rn(q[i * 4 + 2], cv.z);
                q[i * 4 + 3] = __fadd_rn(q[i * 4 + 3], cv.w);
            }
        }
        int n = row0 + m;
        const float4* ep = reinterpret_cast<const float4*>(
            emb + (size_t)n * DIM + dc * 32);
        #pragma unroll
        for (int i = 0; i < 8; i++) {
            float4 ev = __ldg(ep + i);
            float4 ov;
            ov.x = __fadd_rn(ev.x, __fadd_rn(q[i * 4 + 0], -ev.x));
            ov.y = __fadd_rn(ev.y, __fadd_rn(q[i * 4 + 1], -ev.y));
            ov.z = __fadd_rn(ev.z, __fadd_rn(q[i * 4 + 2], -ev.z));
            ov.w = __fadd_rn(ev.w, __fadd_rn(q[i * 4 + 3], -ev.w));
            *reinterpret_cast<float4*>(qout + (size_t)n * DIM + dc * 32 + i * 4) = ov;
        }
    }

    // loss partial -> global accumulator
    if (do_loss) {
        s.lred[tid] = lacc;
        __syncthreads();
        #pragma unroll
        for (int off = NTHR / 2; off >= 1; off >>= 1) {
            if (tid < off) s.lred[tid] += s.lred[tid + off];
            __syncthreads();
        }
        if (tid == 0) atomicAdd(&g_loss, s.lred[0]);
    }
}

extern "C" void kernel_launch(void* const* d_in, const int* in_sizes, int n_in,
                              void* d_out, int out_size) {
    const float* emb = (const float*)d_in[0];
    const float* cbs = (const float*)d_in[1];
    // Defensive: detect order by element counts (emb = 4194304, codebooks = 1048576)
    if (n_in >= 2 && in_sizes[0] == NCB * KCB * DIM && in_sizes[1] == NROWS * DIM) {
        const float* t = emb; emb = cbs; cbs = t;
    }

    float* out     = (float*)d_out;
    float* codes_f = nullptr;
    int*   codes_i = nullptr;
    float* qout    = nullptr;
    float* lossp   = nullptr;

    if (out_size >= CODES_ELEMS + Q_ELEMS + 1) {
        // concatenated [codes, quantized, loss] as float32
        codes_f = out;
        qout    = out + CODES_ELEMS;
        lossp   = out + CODES_ELEMS + Q_ELEMS;
    } else if (out_size == Q_ELEMS) {
        qout = out;
    } else if (out_size == CODES_ELEMS) {
        codes_i = (int*)d_out;
    } else {
        codes_f = out;  // best-effort fallback
    }

    cudaFuncSetAttribute(rvq_main_kernel,
                         cudaFuncAttributeMaxDynamicSharedMemorySize,
                         (int)sizeof(SmemT));

    if (lossp) rvq_zero_kernel<<<1, 1>>>();
    rvq_main_kernel<<<NCTA, NTHR, sizeof(SmemT)>>>(emb, cbs, codes_f, codes_i,
                                                   qout, lossp != nullptr);
    if (lossp) rvq_finish_kernel<<<1, 1>>>(lossp);
}

// round 2
// speedup vs baseline: 1.0456x; 1.0456x over previous
#include <cuda_runtime.h>
#include <cfloat>
#include <cstdint>

// Residual VQ, fused single-kernel implementation, f32x2 packed-FMA mainloop.
// N = 32768 rows of D=128; 8 codebooks of K=1024.
// Each CTA owns MT=64 rows for the whole pipeline (residual lives in smem).

#define NCB   8
#define KCB   1024
#define DIM   128
#define NROWS 32768
#define MT    64          // rows per CTA
#define KT    128         // codes per K-tile
#define NTHR  256
#define NCTA  (NROWS / MT)   // 512

#define CODES_ELEMS (NROWS * NCB)     // 262144
#define Q_ELEMS     (NROWS * DIM)     // 4194304

struct SmemT {
    float  W[DIM][KT];        // codebook tile, transposed [d][k]   64 KB
    float  Rt[DIM][MT];       // residual, transposed [d][m]        32 KB
    float  sqcpart[2][KT];
    float  sqc[KT];
    float  Apart[4][MT];
    float  Arow[MT];
    int    codes_sm[NCB][MT];
    double lred[NTHR];
};

__device__ double g_loss;

__global__ void rvq_zero_kernel() { g_loss = 0.0; }

__global__ void rvq_finish_kernel(float* loss_out) {
    *loss_out = (float)(g_loss * (1.0 / ((double)Q_ELEMS * (double)NCB)));
}

// ---- packed f32x2 helpers (sm_100+ double-rate fp32 path) ----
__device__ __forceinline__ uint64_t dup_f32x2(float x) {
    uint64_t r;
    unsigned u = __float_as_uint(x);
    asm("mov.b64 %0, {%1, %1};" : "=l"(r) : "r"(u));
    return r;
}
__device__ __forceinline__ void fma_f32x2(uint64_t& acc, uint64_t a, uint64_t b) {
    asm("fma.rn.f32x2 %0, %1, %2, %0;" : "+l"(acc) : "l"(a), "l"(b));
}
__device__ __forceinline__ float2 unpack_f32x2(uint64_t v) {
    unsigned lo, hi;
    asm("mov.b64 {%0, %1}, %2;" : "=r"(lo), "=r"(hi) : "l"(v));
    float2 f;
    f.x = __uint_as_float(lo);
    f.y = __uint_as_float(hi);
    return f;
}

__global__ __launch_bounds__(NTHR, 2)
void rvq_main_kernel(const float* __restrict__ emb,
                     const float* __restrict__ cbs,
                     float* __restrict__ codes_f,
                     int*   __restrict__ codes_i,
                     float* __restrict__ qout,
                     int do_loss) {
    extern __shared__ char smem_raw[];
    SmemT& s = *reinterpret_cast<SmemT*>(smem_raw);

    const int tid  = threadIdx.x;
    const int row0 = blockIdx.x * MT;

    // Load embeddings for our 64 rows, transposed into Rt[d][m].
    #pragma unroll
    for (int i = 0; i < 8; i++) {
        int f  = tid + NTHR * i;
        int m  = f & 63;
        int d4 = f >> 6;
        float4 v = __ldg(reinterpret_cast<const float4*>(
            emb + (size_t)(row0 + m) * DIM + d4 * 4));
        s.Rt[d4 * 4 + 0][m] = v.x;
        s.Rt[d4 * 4 + 1][m] = v.y;
        s.Rt[d4 * 4 + 2][m] = v.z;
        s.Rt[d4 * 4 + 3][m] = v.w;
    }
    __syncthreads();

    // Initial A[m] = sum_d r^2
    {
        int m  = tid & 63;
        int dc = tid >> 6;
        float a = 0.f;
        #pragma unroll
        for (int i = 0; i < 32; i++) {
            float v = s.Rt[dc * 32 + i][m];
            a = __fmaf_rn(v, v, a);
        }
        s.Apart[dc][m] = a;
    }
    __syncthreads();
    if (tid < MT)
        s.Arow[tid] = ((s.Apart[0][tid] + s.Apart[1][tid]) + s.Apart[2][tid]) + s.Apart[3][tid];
    __syncthreads();

    double lacc = 0.0;

    const int tk = tid & 31;      // 0..31 : k-column group
    const int tm = tid >> 5;      // 0..7  : m-row group
    const int mb = tm * 8;

    for (int c = 0; c < NCB; c++) {
        const float* cbase = cbs + (size_t)c * KCB * DIM;

        float mval[8];
        int   midx[8];
        #pragma unroll
        for (int r = 0; r < 8; r++) { mval[r] = FLT_MAX; midx[r] = 0; }

        float Areg[8];
        #pragma unroll
        for (int r = 0; r < 8; r++) Areg[r] = s.Arow[mb + r];

        for (int kt = 0; kt < KCB / KT; kt++) {
            __syncthreads();   // previous tile's compute done before overwrite

            // ---- load W tile transposed: W[d][k]
            {
                const int kl = tid & 127;
                const int hh = tid >> 7;
                float sq = 0.f;
                const float* src = cbase + (size_t)(kt * KT + kl) * DIM;
                #pragma unroll
                for (int i = 0; i < 16; i++) {
                    int d4 = hh + 2 * i;
                    float4 v = __ldg(reinterpret_cast<const float4*>(src + d4 * 4));
                    s.W[d4 * 4 + 0][kl] = v.x;
                    s.W[d4 * 4 + 1][kl] = v.y;
                    s.W[d4 * 4 + 2][kl] = v.z;
                    s.W[d4 * 4 + 3][kl] = v.w;
                    sq = __fmaf_rn(v.x, v.x, sq);
                    sq = __fmaf_rn(v.y, v.y, sq);
                    sq = __fmaf_rn(v.z, v.z, sq);
                    sq = __fmaf_rn(v.w, v.w, sq);
                }
                s.sqcpart[hh][kl] = sq;
            }
            __syncthreads();
            if (tid < KT) s.sqc[tid] = s.sqcpart[0][tid] + s.sqcpart[1][tid];
            __syncthreads();

            // ---- GEMM micro-tile: 8 rows x 4 codes per thread, packed f32x2.
            // acc2[rp][j] holds rows (2rp, 2rp+1) for code j.
            uint64_t acc2[4][4];
            #pragma unroll
            for (int rp = 0; rp < 4; rp++)
                #pragma unroll
                for (int j = 0; j < 4; j++) acc2[rp][j] = 0ull;

            const float* pr = &s.Rt[0][mb];
            const float* pw = &s.W[0][tk * 4];
            #pragma unroll 8
            for (int d = 0; d < DIM; d++) {
                // row pairs: 2x 128-bit broadcast loads -> 4 b64 pairs
                ulonglong2 rA = *reinterpret_cast<const ulonglong2*>(pr);
                ulonglong2 rB = *reinterpret_cast<const ulonglong2*>(pr + 4);
                float4 wv = *reinterpret_cast<const float4*>(pw);
                pr += MT;
                pw += KT;
                uint64_t rp4[4] = {rA.x, rA.y, rB.x, rB.y};
                uint64_t wd[4]  = {dup_f32x2(wv.x), dup_f32x2(wv.y),
                                   dup_f32x2(wv.z), dup_f32x2(wv.w)};
                #pragma unroll
                for (int rp = 0; rp < 4; rp++)
                    #pragma unroll
                    for (int j = 0; j < 4; j++)
                        fma_f32x2(acc2[rp][j], rp4[rp], wd[j]);
            }

            // ---- fold into running argmin (k ascending -> first-index tie-break)
            #pragma unroll
            for (int j = 0; j < 4; j++) {
                int   kg = kt * KT + tk * 4 + j;
                float sq = s.sqc[tk * 4 + j];
                #pragma unroll
                for (int rp = 0; rp < 4; rp++) {
                    float2 dot2 = unpack_f32x2(acc2[rp][j]);
                    // d2 = (A - 2*dot) + sqc   (matches reference expression order)
                    float d2a = __fadd_rn(__fmaf_rn(-2.f, dot2.x, Areg[2 * rp + 0]), sq);
                    float d2b = __fadd_rn(__fmaf_rn(-2.f, dot2.y, Areg[2 * rp + 1]), sq);
                    if (d2a < mval[2 * rp + 0]) { mval[2 * rp + 0] = d2a; midx[2 * rp + 0] = kg; }
                    if (d2b < mval[2 * rp + 1]) { mval[2 * rp + 1] = d2b; midx[2 * rp + 1] = kg; }
                }
            }
        }

        // ---- warp argmin reduction over the 32 k-lanes (tie -> smaller index)
        #pragma unroll
        for (int off = 16; off >= 1; off >>= 1) {
            #pragma unroll
            for (int r = 0; r < 8; r++) {
                float ov = __shfl_xor_sync(0xffffffffu, mval[r], off);
                int   oi = __shfl_xor_sync(0xffffffffu, midx[r], off);
                if (ov < mval[r] || (ov == mval[r] && oi < midx[r])) {
                    mval[r] = ov; midx[r] = oi;
                }
            }
        }
        if (tk == 0) {
            #pragma unroll
            for (int r = 0; r < 8; r++) s.codes_sm[c][mb + r] = midx[r];
        }
        __syncthreads();

        // ---- residual update, loss accumulation, next-codebook A
        {
            int m  = tid & 63;
            int dc = tid >> 6;
            int idx = s.codes_sm[c][m];
            const float4* cp = reinterpret_cast<const float4*>(
                cbase + (size_t)idx * DIM + dc * 32);
            float apart = 0.f;
            #pragma unroll
            for (int i = 0; i < 8; i++) {
                float4 cv = __ldg(cp + i);
                int d = dc * 32 + i * 4;
                float r0 = __fadd_rn(s.Rt[d + 0][m], -cv.x);
                float r1 = __fadd_rn(s.Rt[d + 1][m], -cv.y);
                float r2 = __fadd_rn(s.Rt[d + 2][m], -cv.z);
                float r3 = __fadd_rn(s.Rt[d + 3][m], -cv.w);
                s.Rt[d + 0][m] = r0;
                s.Rt[d + 1][m] = r1;
                s.Rt[d + 2][m] = r2;
                s.Rt[d + 3][m] = r3;
                apart = __fmaf_rn(r0, r0, apart);
                apart = __fmaf_rn(r1, r1, apart);
                apart = __fmaf_rn(r2, r2, apart);
                apart = __fmaf_rn(r3, r3, apart);
                lacc += (double)(r0 * r0) + (double)(r1 * r1)
                      + (double)(r2 * r2) + (double)(r3 * r3);
            }
            s.Apart[dc][m] = apart;
        }
        __syncthreads();
        if (tid < MT)
            s.Arow[tid] = ((s.Apart[0][tid] + s.Apart[1][tid]) + s.Apart[2][tid]) + s.Apart[3][tid];
        __syncthreads();
    }

    // ------------------------------------------------------------------
    // Outputs
    // ------------------------------------------------------------------
    if (codes_f != nullptr) {
        for (int v = tid; v < MT * NCB; v += NTHR) {
            int m = v >> 3, c = v & 7;
            codes_f[(size_t)(row0 + m) * NCB + c] = (float)s.codes_sm[c][m];
        }
    }
    if (codes_i != nullptr) {
        for (int v = tid; v < MT * NCB; v += NTHR) {
            int m = v >> 3, c = v & 7;
            codes_i[(size_t)(row0 + m) * NCB + c] = s.codes_sm[c][m];
        }
    }

    if (qout != nullptr) {
        int m  = tid & 63;
        int dc = tid >> 6;
        float q[32];
        #pragma unroll
        for (int i = 0; i < 32; i++) q[i] = 0.f;
        for (int c = 0; c < NCB; c++) {
            int idx = s.codes_sm[c][m];
            const float4* cp = reinterpret_cast<const float4*>(
                cbs + (size_t)c * KCB * DIM + (size_t)idx * DIM + dc * 32);
            #pragma unroll
            for (int i = 0; i < 8; i++) {
                float4 cv = __ldg(cp + i);
                q[i * 4 + 0] = __fadd_rn(q[i * 4 + 0], cv.x);
                q[i * 4 + 1] = __fadd_rn(q[i * 4 + 1], cv.y);
                q[i * 4 + 2] = __fadd_rn(q[i * 4 + 2], cv.z);
                q[i * 4 + 3] = __fadd_rn(q[i * 4 + 3], cv.w);
            }
        }
        int n = row0 + m;
        const float4* ep = reinterpret_cast<const float4*>(
            emb + (size_t)n * DIM + dc * 32);
        #pragma unroll
        for (int i = 0; i < 8; i++) {
            float4 ev = __ldg(ep + i);
            float4 ov;
            ov.x = __fadd_rn(ev.x, __fadd_rn(q[i * 4 + 0], -ev.x));
            ov.y = __fadd_rn(ev.y, __fadd_rn(q[i * 4 + 1], -ev.y));
            ov.z = __fadd_rn(ev.z, __fadd_rn(q[i * 4 + 2], -ev.z));
            ov.w = __fadd_rn(ev.w, __fadd_rn(q[i * 4 + 3], -ev.w));
            *reinterpret_cast<float4*>(qout + (size_t)n * DIM + dc * 32 + i * 4) = ov;
        }
    }

    if (do_loss) {
        s.lred[tid] = lacc;
        __syncthreads();
        #pragma unroll
        for (int off = NTHR / 2; off >= 1; off >>= 1) {
            if (tid < off) s.lred[tid] += s.lred[tid + off];
            __syncthreads();
        }
        if (tid == 0) atomicAdd(&g_loss, s.lred[0]);
    }
}

extern "C" void kernel_launch(void* const* d_in, const int* in_sizes, int n_in,
                              void* d_out, int out_size) {
    const float* emb = (const float*)d_in[0];
    const float* cbs = (const float*)d_in[1];
    if (n_in >= 2 && in_sizes[0] == NCB * KCB * DIM && in_sizes[1] == NROWS * DIM) {
        const float* t = emb; emb = cbs; cbs = t;
    }

    float* out     = (float*)d_out;
    float* codes_f = nullptr;
    int*   codes_i = nullptr;
    float* qout    = nullptr;
    float* lossp   = nullptr;

    if (out_size >= CODES_ELEMS + Q_ELEMS + 1) {
        codes_f = out;
        qout    = out + CODES_ELEMS;
        lossp   = out + CODES_ELEMS + Q_ELEMS;
    } else if (out_size == Q_ELEMS) {
        qout = out;
    } else if (out_size == CODES_ELEMS) {
        codes_i = (int*)d_out;
    } else {
        codes_f = out;
    }

    cudaFuncSetAttribute(rvq_main_kernel,
                         cudaFuncAttributeMaxDynamicSharedMemorySize,
                         (int)sizeof(SmemT));

    if (lossp) rvq_zero_kernel<<<1, 1>>>();
    rvq_main_kernel<<<NCTA, NTHR, sizeof(SmemT)>>>(emb, cbs, codes_f, codes_i,
                                                   qout, lossp != nullptr);
    if (lossp) rvq_finish_kernel<<<1, 1>>>(lossp);
}